// round 11
// baseline (speedup 1.0000x reference)
#include <cuda_runtime.h>
#include <cuda_bf16.h>
#include <math.h>
#include <stdint.h>

#define Bq 128
#define Sq 1024
#define Dq 512
#define Hq 512

// ---------------- scratch (device globals; no allocs allowed) ---------------
__device__ float g_inp [Bq * Hq];
__device__ float g_att [Bq * Sq];
__device__ float g_cbar[Bq * Dq];
__device__ float g_cbar_part[4][Bq * Dq];
__device__ __nv_bfloat16 g_ctx_h[Bq * Sq * Dq];   // 128 MB
__device__ __nv_bfloat16 g_ctx_l[Bq * Sq * Dq];   // 128 MB
__device__ __nv_bfloat16 g_w_h  [Hq * Dq];
__device__ __nv_bfloat16 g_w_l  [Hq * Dq];

// ---------------- smem layout for k_mma (bytes) ------------------------------
// BK=32 slabs: 128 rows x 80 B (64 B data + 16 B pad): conflict-free ldmatrix.
#define RS      80
#define TSZ     (128 * RS)          // 10240 per tile per buffer
#define OF_AH   0                   // [2][TSZ]
#define OF_AL   20480
#define OF_BH   40960
#define OF_BL   61440
#define OF_PRE  81920               // 512 floats
#define OF_V    83968               // 512 floats
#define OF_ATTW 86016               // 4 x 128 floats
#define SMEM_SZ 88064

// ---------------- PTX helpers ------------------------------------------------
__device__ __forceinline__ uint32_t smem_u32(const void* p) {
    uint32_t a;
    asm("{ .reg .u64 t; cvta.to.shared.u64 t, %1; cvt.u32.u64 %0, t; }"
        : "=r"(a) : "l"(p));
    return a;
}
__device__ __forceinline__ void cp16(uint32_t dst, const void* src) {
    asm volatile("cp.async.cg.shared.global [%0], [%1], 16;"
                 :: "r"(dst), "l"(src) : "memory");
}
__device__ __forceinline__ void cp_commit() {
    asm volatile("cp.async.commit_group;" ::: "memory");
}
__device__ __forceinline__ void cp_wait0() {
    asm volatile("cp.async.wait_group 0;" ::: "memory");
}
__device__ __forceinline__ void ldsm_x4(uint32_t& r0, uint32_t& r1,
                                        uint32_t& r2, uint32_t& r3,
                                        uint32_t addr) {
    asm volatile("ldmatrix.sync.aligned.m8n8.x4.shared.b16 {%0,%1,%2,%3}, [%4];"
                 : "=r"(r0), "=r"(r1), "=r"(r2), "=r"(r3) : "r"(addr));
}
__device__ __forceinline__ void mma16816(float* c, const uint32_t* a,
                                         const uint32_t* b) {
    asm volatile(
        "mma.sync.aligned.m16n8k16.row.col.f32.bf16.bf16.f32 "
        "{%0,%1,%2,%3}, {%4,%5,%6,%7}, {%8,%9}, {%0,%1,%2,%3};"
        : "+f"(c[0]), "+f"(c[1]), "+f"(c[2]), "+f"(c[3])
        : "r"(a[0]), "r"(a[1]), "r"(a[2]), "r"(a[3]), "r"(b[0]), "r"(b[1]));
}

// ---------------- fast tanh: FMA-only rational, no MUFU ----------------------
__device__ __forceinline__ float fast_tanh(float x) {
    x = fminf(fmaxf(x, -7.99881172f), 7.99881172f);
    const float x2 = x * x;
    float p = fmaf(x2, -2.76076847742355e-16f, 2.00018790482477e-13f);
    p = fmaf(p, x2, -8.60467152213735e-11f);
    p = fmaf(p, x2,  5.12229709037114e-08f);
    p = fmaf(p, x2,  1.48572235717979e-05f);
    p = fmaf(p, x2,  6.37261928875436e-04f);
    p = fmaf(p, x2,  4.89352455891786e-03f);
    p *= x;
    float q = fmaf(x2, 1.19825839466702e-06f, 1.18534705686654e-04f);
    q = fmaf(q, x2, 2.26843463243900e-03f);
    q = fmaf(q, x2, 4.89352518554385e-03f);
    float r = __uint_as_float(0x7EF311C3u - __float_as_uint(q));
    r = r * (2.0f - q * r);
    r = r * (2.0f - q * r);
    r = r * (2.0f - q * r);
    return p * r;
}

// ---------------------------------------------------------------------------
// bf16 hi/lo split
// ---------------------------------------------------------------------------
__device__ __forceinline__ uint32_t pack_bf2(float a, float b) {
    __nv_bfloat162 t;
    t.x = __float2bfloat16(a);
    t.y = __float2bfloat16(b);
    return *(uint32_t*)&t;
}
__global__ void k_split(const float4* __restrict__ src,
                        uint2* __restrict__ dh, uint2* __restrict__ dl, int n4) {
    int i = blockIdx.x * 256 + threadIdx.x;
    if (i >= n4) return;
    float4 v = src[i];
    float h0 = __bfloat162float(__float2bfloat16(v.x));
    float h1 = __bfloat162float(__float2bfloat16(v.y));
    float h2 = __bfloat162float(__float2bfloat16(v.z));
    float h3 = __bfloat162float(__float2bfloat16(v.w));
    uint2 H, L;
    H.x = pack_bf2(h0, h1);            H.y = pack_bf2(h2, h3);
    L.x = pack_bf2(v.x - h0, v.y - h1);
    L.y = pack_bf2(v.z - h2, v.w - h3);
    dh[i] = H;  dl[i] = L;
}

// ---------------------------------------------------------------------------
// k_lin
// ---------------------------------------------------------------------------
__global__ void k_lin(const float* __restrict__ X, const float* __restrict__ W,
                      const float* __restrict__ bias, float* __restrict__ out) {
    __shared__ float xs[Dq];
    const int b = blockIdx.x;
    for (int d = threadIdx.x; d < Dq; d += blockDim.x) xs[d] = X[b * Dq + d];
    __syncthreads();
    for (int h = threadIdx.x; h < Hq; h += blockDim.x) {
        const float4* w = (const float4*)(W + (size_t)h * Dq);
        float acc = 0.f;
#pragma unroll 8
        for (int i = 0; i < Dq / 4; i++) {
            float4 wv = w[i];
            acc += wv.x * xs[4 * i + 0] + wv.y * xs[4 * i + 1]
                 + wv.z * xs[4 * i + 2] + wv.w * xs[4 * i + 3];
        }
        out[b * Hq + h] = acc + bias[h];
    }
}

// ---------------------------------------------------------------------------
// HMMA fused score GEMM. grid(8, 128), 512 threads (16 warps, 4m x 4n of
// 32x32 warp tiles). 64 steps = 4 h-chunks x 16 K-slabs of 32. One sync/step.
// Per step: ldsm f0 (k16) + ldsm f1 (k16) up front, then two 24-MMA bursts —
// f1's ldmatrix overlaps f0's MMAs via scoreboards (fits in regs with 32-reg
// acc). Products ordered outermost: 8 indep MMAs between acc reuses.
// ---------------------------------------------------------------------------
__global__ void __launch_bounds__(512)
k_mma(const float* __restrict__ b_ctx, const float* __restrict__ V) {
    extern __shared__ __align__(16) char smem[];
    const uint32_t sb = smem_u32(smem);
    const int tid  = threadIdx.x;
    const int wid  = tid >> 5;
    const int lane = tid & 31;
    const int wm   = wid & 3;        // rows wm*32..+31
    const int wn   = wid >> 2;       // cols wn*32..+31
    const int b    = blockIdx.y;
    const int s0   = blockIdx.x * 128;

    float* pre_s = (float*)(smem + OF_PRE);
    float* V_s   = (float*)(smem + OF_V);
    float* attw  = (float*)(smem + OF_ATTW);

    if (tid < Hq) {
        pre_s[tid] = g_inp[b * Hq + tid] + b_ctx[tid];
        V_s[tid]   = V[tid];
    }

    // per-thread staging: row = tid>>2 (0..127), seg = tid&3 (16B each)
    const int srow = tid >> 2;
    const int sseg = tid & 3;
    const uint32_t sdst = sb + (uint32_t)(srow * RS + sseg * 16);
    const __nv_bfloat16* pAh = g_ctx_h + ((size_t)(b * Sq) + s0 + srow) * Dq + sseg * 8;
    const __nv_bfloat16* pAl = g_ctx_l + ((size_t)(b * Sq) + s0 + srow) * Dq + sseg * 8;
    const __nv_bfloat16* pBh = g_w_h + (size_t)srow * Dq + sseg * 8;
    const __nv_bfloat16* pBl = g_w_l + (size_t)srow * Dq + sseg * 8;

    // ldmatrix per-lane byte offsets (m16k16 A tiles, n16k16 B tiles)
    const uint32_t aoff = (uint32_t)((wm * 32 + (lane & 15)) * RS + (lane >> 4) * 16);
    const uint32_t boff = (uint32_t)((wn * 32 + (lane & 15)) * RS + (lane >> 4) * 16);

    float acc[2][4][4];
#pragma unroll
    for (int mi = 0; mi < 2; mi++)
#pragma unroll
        for (int nj = 0; nj < 4; nj++)
#pragma unroll
            for (int r = 0; r < 4; r++) acc[mi][nj][r] = 0.f;
    float p[4] = {0.f, 0.f, 0.f, 0.f};

    __syncthreads();   // pre_s/V_s ready

    auto stage = [&](int g, int buf) {
        const int ka = (g & 15) * 32;
        const int hb = (g >> 4) * 128;
        const uint32_t d = sdst + (uint32_t)(buf * TSZ);
        cp16(d + OF_AH, pAh + ka);
        cp16(d + OF_AL, pAl + ka);
        cp16(d + OF_BH, pBh + (size_t)hb * Dq + ka);
        cp16(d + OF_BL, pBl + (size_t)hb * Dq + ka);
    };

    stage(0, 0);
    cp_commit();

    for (int g = 0; g < 64; g++) {
        const int buf = g & 1;
        cp_wait0();
        __syncthreads();
        if (g < 63) { stage(g + 1, buf ^ 1); cp_commit(); }

        const uint32_t bo = sb + (uint32_t)(buf * TSZ);

        // ---- fragment set f0 (k-slab half 0): hi first, then lo ----
        uint32_t ah0[2][4], al0[2][4], bh0[4][2], bl0[4][2];
        uint32_t ah1[2][4], al1[2][4], bh1[4][2], bl1[4][2];
#pragma unroll
        for (int mi = 0; mi < 2; mi++)
            ldsm_x4(ah0[mi][0], ah0[mi][1], ah0[mi][2], ah0[mi][3],
                    bo + OF_AH + aoff + mi * (16 * RS));
        {
            uint32_t r0, r1, r2, r3;
            ldsm_x4(r0, r1, r2, r3, bo + OF_BH + boff);
            bh0[0][0] = r0; bh0[0][1] = r2; bh0[1][0] = r1; bh0[1][1] = r3;
            ldsm_x4(r0, r1, r2, r3, bo + OF_BH + boff + 16 * RS);
            bh0[2][0] = r0; bh0[2][1] = r2; bh0[3][0] = r1; bh0[3][1] = r3;
        }
#pragma unroll
        for (int mi = 0; mi < 2; mi++)
            ldsm_x4(al0[mi][0], al0[mi][1], al0[mi][2], al0[mi][3],
                    bo + OF_AL + aoff + mi * (16 * RS));
        {
            uint32_t r0, r1, r2, r3;
            ldsm_x4(r0, r1, r2, r3, bo + OF_BL + boff);
            bl0[0][0] = r0; bl0[0][1] = r2; bl0[1][0] = r1; bl0[1][1] = r3;
            ldsm_x4(r0, r1, r2, r3, bo + OF_BL + boff + 16 * RS);
            bl0[2][0] = r0; bl0[2][1] = r2; bl0[3][0] = r1; bl0[3][1] = r3;
        }
        // ---- fragment set f1 (k-slab half 1) — overlaps f0's MMA burst ----
#pragma unroll
        for (int mi = 0; mi < 2; mi++)
            ldsm_x4(ah1[mi][0], ah1[mi][1], ah1[mi][2], ah1[mi][3],
                    bo + OF_AH + aoff + mi * (16 * RS) + 32);
        {
            uint32_t r0, r1, r2, r3;
            ldsm_x4(r0, r1, r2, r3, bo + OF_BH + boff + 32);
            bh1[0][0] = r0; bh1[0][1] = r2; bh1[1][0] = r1; bh1[1][1] = r3;
            ldsm_x4(r0, r1, r2, r3, bo + OF_BH + boff + 16 * RS + 32);
            bh1[2][0] = r0; bh1[2][1] = r2; bh1[3][0] = r1; bh1[3][1] = r3;
        }
#pragma unroll
        for (int mi = 0; mi < 2; mi++)
            ldsm_x4(al1[mi][0], al1[mi][1], al1[mi][2], al1[mi][3],
                    bo + OF_AL + aoff + mi * (16 * RS) + 32);
        {
            uint32_t r0, r1, r2, r3;
            ldsm_x4(r0, r1, r2, r3, bo + OF_BL + boff + 32);
            bl1[0][0] = r0; bl1[0][1] = r2; bl1[1][0] = r1; bl1[1][1] = r3;
            ldsm_x4(r0, r1, r2, r3, bo + OF_BL + boff + 16 * RS + 32);
            bl1[2][0] = r0; bl1[2][1] = r2; bl1[3][0] = r1; bl1[3][1] = r3;
        }

        // ---- MMA bursts: f0 then f1, product-outermost ----
#pragma unroll
        for (int mi = 0; mi < 2; mi++)
#pragma unroll
            for (int nj = 0; nj < 4; nj++)
                mma16816(acc[mi][nj], ah0[mi], bh0[nj]);
#pragma unroll
        for (int mi = 0; mi < 2; mi++)
#pragma unroll
            for (int nj = 0; nj < 4; nj++)
                mma16816(acc[mi][nj], ah0[mi], bl0[nj]);
#pragma unroll
        for (int mi = 0; mi < 2; mi++)
#pragma unroll
            for (int nj = 0; nj < 4; nj++)
                mma16816(acc[mi][nj], al0[mi], bh0[nj]);
#pragma unroll
        for (int mi = 0; mi < 2; mi++)
#pragma unroll
            for (int nj = 0; nj < 4; nj++)
                mma16816(acc[mi][nj], ah1[mi], bh1[nj]);
#pragma unroll
        for (int mi = 0; mi < 2; mi++)
#pragma unroll
            for (int nj = 0; nj < 4; nj++)
                mma16816(acc[mi][nj], ah1[mi], bl1[nj]);
#pragma unroll
        for (int mi = 0; mi < 2; mi++)
#pragma unroll
            for (int nj = 0; nj < 4; nj++)
                mma16816(acc[mi][nj], al1[mi], bh1[nj]);

        if ((g & 15) == 15) {
            // epilogue for h-chunk: p += V * tanh(pre + C); reset acc.
            const int hc = (g >> 4) * 128;
            const int nb = hc + wn * 32 + (lane & 3) * 2;
#pragma unroll
            for (int mi = 0; mi < 2; mi++)
#pragma unroll
                for (int nj = 0; nj < 4; nj++) {
                    const int n0 = nb + nj * 8;
                    const float v0 = V_s[n0],     q0 = pre_s[n0];
                    const float v1 = V_s[n0 + 1], q1 = pre_s[n0 + 1];
                    p[mi * 2] += v0 * fast_tanh(q0 + acc[mi][nj][0])
                               + v1 * fast_tanh(q1 + acc[mi][nj][1]);
                    p[mi * 2 + 1] += v0 * fast_tanh(q0 + acc[mi][nj][2])
                                   + v1 * fast_tanh(q1 + acc[mi][nj][3]);
                    acc[mi][nj][0] = 0.f; acc[mi][nj][1] = 0.f;
                    acc[mi][nj][2] = 0.f; acc[mi][nj][3] = 0.f;
                }
        }
    }

    // reduce over lane quads (cols), combine the 4 n-warps via smem
#pragma unroll
    for (int i = 0; i < 4; i++) {
        p[i] += __shfl_xor_sync(0xffffffffu, p[i], 1);
        p[i] += __shfl_xor_sync(0xffffffffu, p[i], 2);
    }
    if ((lane & 3) == 0) {
#pragma unroll
        for (int mi = 0; mi < 2; mi++)
#pragma unroll
            for (int hf = 0; hf < 2; hf++) {
                const int row = wm * 32 + mi * 16 + (lane >> 2) + hf * 8;
                attw[wn * 128 + row] = p[mi * 2 + hf];
            }
    }
    __syncthreads();
    if (tid < 128)
        g_att[b * Sq + s0 + tid] = (attw[tid] + attw[128 + tid])
                                 + (attw[256 + tid] + attw[384 + tid]);
}

// ---------------------------------------------------------------------------
// Masked softmax (mask int32).
// ---------------------------------------------------------------------------
__global__ void k_softmax(const int* __restrict__ mask,
                          float* __restrict__ alpha) {
    const int b = blockIdx.x, tid = threadIdx.x;
    __shared__ float red[8];
    float v[4];
#pragma unroll
    for (int i = 0; i < 4; i++) {
        const int s = tid + i * 256;
        const float a = g_att[b * Sq + s];
        v[i] = mask[b * Sq + s] ? -INFINITY : a;
    }
    float m = fmaxf(fmaxf(v[0], v[1]), fmaxf(v[2], v[3]));
#pragma unroll
    for (int o = 16; o; o >>= 1) m = fmaxf(m, __shfl_xor_sync(~0u, m, o));
    if ((tid & 31) == 0) red[tid >> 5] = m;
    __syncthreads();
    m = red[0];
#pragma unroll
    for (int i = 1; i < 8; i++) m = fmaxf(m, red[i]);
    __syncthreads();
    float e[4], sum = 0.f;
#pragma unroll
    for (int i = 0; i < 4; i++) { e[i] = expf(v[i] - m); sum += e[i]; }
#pragma unroll
    for (int o = 16; o; o >>= 1) sum += __shfl_xor_sync(~0u, sum, o);
    if ((tid & 31) == 0) red[tid >> 5] = sum;
    __syncthreads();
    sum = 0.f;
#pragma unroll
    for (int i = 0; i < 8; i++) sum += red[i];
    const float inv = 1.f / sum;
#pragma unroll
    for (int i = 0; i < 4; i++)
        alpha[b * Sq + tid + i * 256] = e[i] * inv;
}

// ---------------------------------------------------------------------------
// c_bar partials + reduce (deterministic).
// ---------------------------------------------------------------------------
__global__ void k_cbar(const float* __restrict__ context,
                       const float* __restrict__ alpha) {
    const int b  = blockIdx.z;
    const int sc = blockIdx.y;
    const int d  = blockIdx.x * 256 + threadIdx.x;
    const int s0 = sc * 256;
    __shared__ float al[256];
    al[threadIdx.x] = alpha[b * Sq + s0 + threadIdx.x];
    __syncthreads();
    const float* cp = context + ((size_t)b * Sq + s0) * Dq + d;
    float a0 = 0.f, a1 = 0.f, a2 = 0.f, a3 = 0.f;
    for (int s = 0; s < 256; s += 4) {
        a0 += al[s + 0] * cp[(size_t)(s + 0) * Dq];
        a1 += al[s + 1] * cp[(size_t)(s + 1) * Dq];
        a2 += al[s + 2] * cp[(size_t)(s + 2) * Dq];
        a3 += al[s + 3] * cp[(size_t)(s + 3) * Dq];
    }
    g_cbar_part[sc][b * Dq + d] = (a0 + a1) + (a2 + a3);
}
__global__ void k_cbar_reduce() {
    const int i = blockIdx.x * 256 + threadIdx.x;
    g_cbar[i] = (g_cbar_part[0][i] + g_cbar_part[1][i])
              + (g_cbar_part[2][i] + g_cbar_part[3][i]);
}

// ---------------------------------------------------------------------------
extern "C" void kernel_launch(void* const* d_in, const int* in_sizes, int n_in,
                              void* d_out, int out_size) {
    const float* input   = (const float*)d_in[0];
    const float* context = (const float*)d_in[1];
    const int*   mask    = (const int*)d_in[2];
    const float* W_in    = (const float*)d_in[3];
    const float* b_in    = (const float*)d_in[4];
    const float* W_ctx   = (const float*)d_in[5];
    const float* b_ctx   = (const float*)d_in[6];
    const float* V       = (const float*)d_in[7];

    float* hidden = (float*)d_out;
    float* alpha  = (float*)d_out + Bq * Hq;

    float *p_inp = nullptr, *p_cbar = nullptr;
    void  *p_ch = nullptr, *p_cl = nullptr, *p_wh = nullptr, *p_wl = nullptr;
    cudaGetSymbolAddress((void**)&p_inp,  g_inp);
    cudaGetSymbolAddress((void**)&p_cbar, g_cbar);
    cudaGetSymbolAddress(&p_ch, g_ctx_h);
    cudaGetSymbolAddress(&p_cl, g_ctx_l);
    cudaGetSymbolAddress(&p_wh, g_w_h);
    cudaGetSymbolAddress(&p_wl, g_w_l);

    cudaFuncSetAttribute(k_mma, cudaFuncAttributeMaxDynamicSharedMemorySize,
                         SMEM_SZ);

    const int n4c = Bq * Sq * Dq / 4;
    const int n4w = Hq * Dq / 4;
    k_split<<<n4c / 256, 256>>>((const float4*)context,
                                (uint2*)p_ch, (uint2*)p_cl, n4c);
    k_split<<<n4w / 256, 256>>>((const float4*)W_ctx,
                                (uint2*)p_wh, (uint2*)p_wl, n4w);
    k_lin  <<<Bq, 256>>>(input, W_in, b_in, p_inp);
    k_mma  <<<dim3(Sq / 128, Bq), 512, SMEM_SZ>>>(b_ctx, V);
    k_softmax<<<Bq, 256>>>(mask, alpha);
    k_cbar <<<dim3(2, 4, Bq), 256>>>(context, alpha);
    k_cbar_reduce<<<Bq * Dq / 256, 256>>>();
    k_lin  <<<Bq, 256>>>(p_cbar, W_ctx, b_ctx, hidden);
}

// round 12
// speedup vs baseline: 1.5143x; 1.5143x over previous
#include <cuda_runtime.h>
#include <cuda_bf16.h>
#include <math.h>
#include <stdint.h>

#define Bq 128
#define Sq 1024
#define Dq 512
#define Hq 512

// ---------------- scratch (device globals; no allocs allowed) ---------------
__device__ float g_inp [Bq * Hq];
__device__ float g_att [Bq * Sq];
__device__ float g_cbar[Bq * Dq];
__device__ float g_cbar_part[4][Bq * Dq];
__device__ int   g_sidx[Bq * Sq];     // compacted unmasked s-indices per b
__device__ int   g_cnt [Bq];          // unmasked count per b
__device__ __nv_bfloat16 g_ctx_h[Bq * Sq * Dq];   // 128 MB
__device__ __nv_bfloat16 g_ctx_l[Bq * Sq * Dq];   // 128 MB
__device__ __nv_bfloat16 g_w_h  [Hq * Dq];
__device__ __nv_bfloat16 g_w_l  [Hq * Dq];

// ---------------- smem layout for k_mma (bytes) ------------------------------
#define RS      80
#define TSZ     (128 * RS)          // 10240 per tile per buffer
#define OF_AH   0                   // [2][TSZ]
#define OF_AL   20480
#define OF_BH   40960
#define OF_BL   61440
#define OF_PRE  81920               // 512 floats
#define OF_V    83968               // 512 floats
#define OF_ATTW 86016               // 4 x 128 floats
#define SMEM_SZ 88064

// ---------------- PTX helpers ------------------------------------------------
__device__ __forceinline__ uint32_t smem_u32(const void* p) {
    uint32_t a;
    asm("{ .reg .u64 t; cvta.to.shared.u64 t, %1; cvt.u32.u64 %0, t; }"
        : "=r"(a) : "l"(p));
    return a;
}
__device__ __forceinline__ void cp16(uint32_t dst, const void* src) {
    asm volatile("cp.async.cg.shared.global [%0], [%1], 16;"
                 :: "r"(dst), "l"(src) : "memory");
}
__device__ __forceinline__ void cp_commit() {
    asm volatile("cp.async.commit_group;" ::: "memory");
}
__device__ __forceinline__ void cp_wait0() {
    asm volatile("cp.async.wait_group 0;" ::: "memory");
}
__device__ __forceinline__ void ldsm_x4(uint32_t& r0, uint32_t& r1,
                                        uint32_t& r2, uint32_t& r3,
                                        uint32_t addr) {
    asm volatile("ldmatrix.sync.aligned.m8n8.x4.shared.b16 {%0,%1,%2,%3}, [%4];"
                 : "=r"(r0), "=r"(r1), "=r"(r2), "=r"(r3) : "r"(addr));
}
__device__ __forceinline__ void mma16816(float* c, const uint32_t* a,
                                         const uint32_t* b) {
    asm volatile(
        "mma.sync.aligned.m16n8k16.row.col.f32.bf16.bf16.f32 "
        "{%0,%1,%2,%3}, {%4,%5,%6,%7}, {%8,%9}, {%0,%1,%2,%3};"
        : "+f"(c[0]), "+f"(c[1]), "+f"(c[2]), "+f"(c[3])
        : "r"(a[0]), "r"(a[1]), "r"(a[2]), "r"(a[3]), "r"(b[0]), "r"(b[1]));
}

// ---------------- fast tanh: FMA-only rational, no MUFU ----------------------
__device__ __forceinline__ float fast_tanh(float x) {
    x = fminf(fmaxf(x, -7.99881172f), 7.99881172f);
    const float x2 = x * x;
    float p = fmaf(x2, -2.76076847742355e-16f, 2.00018790482477e-13f);
    p = fmaf(p, x2, -8.60467152213735e-11f);
    p = fmaf(p, x2,  5.12229709037114e-08f);
    p = fmaf(p, x2,  1.48572235717979e-05f);
    p = fmaf(p, x2,  6.37261928875436e-04f);
    p = fmaf(p, x2,  4.89352455891786e-03f);
    p *= x;
    float q = fmaf(x2, 1.19825839466702e-06f, 1.18534705686654e-04f);
    q = fmaf(q, x2, 2.26843463243900e-03f);
    q = fmaf(q, x2, 4.89352518554385e-03f);
    float r = __uint_as_float(0x7EF311C3u - __float_as_uint(q));
    r = r * (2.0f - q * r);
    r = r * (2.0f - q * r);
    r = r * (2.0f - q * r);
    return p * r;
}

// ---------------------------------------------------------------------------
// k_compact: per-b stable compaction of unmasked s indices (ballot scan).
// grid(Bq), 1024 threads.
// ---------------------------------------------------------------------------
__global__ void k_compact(const int* __restrict__ mask) {
    const int b = blockIdx.x, tid = threadIdx.x;
    const int wid = tid >> 5, lane = tid & 31;
    __shared__ int wcnt[32];
    const int um = (mask[b * Sq + tid] == 0);
    const unsigned bal = __ballot_sync(0xffffffffu, um);
    if (lane == 0) wcnt[wid] = __popc(bal);
    __syncthreads();
    if (tid == 0) {
        int t = 0;
        for (int i = 0; i < 32; i++) { int c = wcnt[i]; wcnt[i] = t; t += c; }
        g_cnt[b] = t;
    }
    __syncthreads();
    if (um) {
        const int pos = wcnt[wid] + __popc(bal & ((1u << lane) - 1u));
        g_sidx[b * Sq + pos] = tid;
    }
}

// ---------------------------------------------------------------------------
// bf16 hi/lo split helpers
// ---------------------------------------------------------------------------
__device__ __forceinline__ uint32_t pack_bf2(float a, float b) {
    __nv_bfloat162 t;
    t.x = __float2bfloat16(a);
    t.y = __float2bfloat16(b);
    return *(uint32_t*)&t;
}
__device__ __forceinline__ void split4(float4 v, uint2& H, uint2& L) {
    float h0 = __bfloat162float(__float2bfloat16(v.x));
    float h1 = __bfloat162float(__float2bfloat16(v.y));
    float h2 = __bfloat162float(__float2bfloat16(v.z));
    float h3 = __bfloat162float(__float2bfloat16(v.w));
    H.x = pack_bf2(h0, h1);            H.y = pack_bf2(h2, h3);
    L.x = pack_bf2(v.x - h0, v.y - h1);
    L.y = pack_bf2(v.z - h2, v.w - h3);
}

// context split, skipping masked rows (their data is never read)
__global__ void k_split_ctx(const float4* __restrict__ src,
                            uint2* __restrict__ dh, uint2* __restrict__ dl,
                            const int* __restrict__ mask) {
    const int i = blockIdx.x * 256 + threadIdx.x;     // n4 = 16M
    const int s = (i >> 7) & 1023;
    const int b = i >> 17;
    if (mask[b * Sq + s]) return;
    uint2 H, L;
    split4(src[i], H, L);
    dh[i] = H;  dl[i] = L;
}

__global__ void k_split_w(const float4* __restrict__ src,
                          uint2* __restrict__ dh, uint2* __restrict__ dl,
                          int n4) {
    const int i = blockIdx.x * 256 + threadIdx.x;
    if (i >= n4) return;
    uint2 H, L;
    split4(src[i], H, L);
    dh[i] = H;  dl[i] = L;
}

// ---------------------------------------------------------------------------
// k_lin
// ---------------------------------------------------------------------------
__global__ void k_lin(const float* __restrict__ X, const float* __restrict__ W,
                      const float* __restrict__ bias, float* __restrict__ out) {
    __shared__ float xs[Dq];
    const int b = blockIdx.x;
    for (int d = threadIdx.x; d < Dq; d += blockDim.x) xs[d] = X[b * Dq + d];
    __syncthreads();
    for (int h = threadIdx.x; h < Hq; h += blockDim.x) {
        const float4* w = (const float4*)(W + (size_t)h * Dq);
        float acc = 0.f;
#pragma unroll 8
        for (int i = 0; i < Dq / 4; i++) {
            float4 wv = w[i];
            acc += wv.x * xs[4 * i + 0] + wv.y * xs[4 * i + 1]
                 + wv.z * xs[4 * i + 2] + wv.w * xs[4 * i + 3];
        }
        out[b * Hq + h] = acc + bias[h];
    }
}

// ---------------------------------------------------------------------------
// HMMA fused score GEMM over COMPACTED unmasked rows.
// grid(8, 128), 256 threads (8 warps, 2m x 4n of 64x32 tiles). Tiles with
// s0 >= cnt[b] exit immediately (~46% of launches). Rows gathered via g_sidx.
// ---------------------------------------------------------------------------
__global__ void __launch_bounds__(256)
k_mma(const float* __restrict__ b_ctx, const float* __restrict__ V) {
    extern __shared__ __align__(16) char smem[];
    const int b   = blockIdx.y;
    const int s0  = blockIdx.x * 128;
    const int cnt = g_cnt[b];
    if (s0 >= cnt) return;

    const uint32_t sb = smem_u32(smem);
    const int tid  = threadIdx.x;
    const int wid  = tid >> 5;
    const int lane = tid & 31;
    const int wm   = wid & 1;        // rows wm*64..+63
    const int wn   = wid >> 1;       // cols wn*32..+31

    float* pre_s = (float*)(smem + OF_PRE);
    float* V_s   = (float*)(smem + OF_V);
    float* attw  = (float*)(smem + OF_ATTW);

    for (int i = tid; i < Hq; i += 256) {
        pre_s[i] = g_inp[b * Hq + i] + b_ctx[i];
        V_s[i]   = V[i];
    }

    // per-thread staging: row = tid>>1 (0..127) GATHERED, two 16B segs
    const int srow = tid >> 1;
    const int sseg = (tid & 1) * 2;
    const int gidx = s0 + srow < cnt ? s0 + srow : cnt - 1;
    const int grow = g_sidx[b * Sq + gidx];
    const uint32_t sdst = sb + (uint32_t)(srow * RS + sseg * 16);
    const __nv_bfloat16* pAh = g_ctx_h + ((size_t)(b * Sq) + grow) * Dq + sseg * 8;
    const __nv_bfloat16* pAl = g_ctx_l + ((size_t)(b * Sq) + grow) * Dq + sseg * 8;
    const __nv_bfloat16* pBh = g_w_h + (size_t)srow * Dq + sseg * 8;
    const __nv_bfloat16* pBl = g_w_l + (size_t)srow * Dq + sseg * 8;

    const uint32_t aoff = (uint32_t)((wm * 64 + (lane & 15)) * RS + (lane >> 4) * 16);
    const uint32_t boff = (uint32_t)((wn * 32 + (lane & 15)) * RS + (lane >> 4) * 16);

    float acc[4][4][4];
#pragma unroll
    for (int mi = 0; mi < 4; mi++)
#pragma unroll
        for (int nj = 0; nj < 4; nj++)
#pragma unroll
            for (int r = 0; r < 4; r++) acc[mi][nj][r] = 0.f;
    float p[8];
#pragma unroll
    for (int i = 0; i < 8; i++) p[i] = 0.f;

    __syncthreads();

    auto stage = [&](int g, int buf) {
        const int ka = (g & 15) * 32;
        const int hb = (g >> 4) * 128;
        const uint32_t d = sdst + (uint32_t)(buf * TSZ);
        const __nv_bfloat16* a_h = pAh + ka;
        const __nv_bfloat16* a_l = pAl + ka;
        const __nv_bfloat16* b_h = pBh + (size_t)hb * Dq + ka;
        const __nv_bfloat16* b_l = pBl + (size_t)hb * Dq + ka;
        cp16(d + OF_AH,      a_h);
        cp16(d + OF_AH + 16, a_h + 8);
        cp16(d + OF_AL,      a_l);
        cp16(d + OF_AL + 16, a_l + 8);
        cp16(d + OF_BH,      b_h);
        cp16(d + OF_BH + 16, b_h + 8);
        cp16(d + OF_BL,      b_l);
        cp16(d + OF_BL + 16, b_l + 8);
    };

    stage(0, 0);
    cp_commit();

    for (int g = 0; g < 64; g++) {
        const int buf = g & 1;
        cp_wait0();
        __syncthreads();
        if (g < 63) { stage(g + 1, buf ^ 1); cp_commit(); }

        const uint32_t bo = sb + (uint32_t)(buf * TSZ);
#pragma unroll
        for (int kk = 0; kk < 2; kk++) {
            const uint32_t kb = kk * 32;
            uint32_t ah[4][4], al[4][4], bh[4][2], bl[4][2];
#pragma unroll
            for (int mi = 0; mi < 4; mi++) {
                ldsm_x4(ah[mi][0], ah[mi][1], ah[mi][2], ah[mi][3],
                        bo + OF_AH + aoff + mi * (16 * RS) + kb);
                ldsm_x4(al[mi][0], al[mi][1], al[mi][2], al[mi][3],
                        bo + OF_AL + aoff + mi * (16 * RS) + kb);
            }
#pragma unroll
            for (int ni = 0; ni < 2; ni++) {
                uint32_t r0, r1, r2, r3;
                ldsm_x4(r0, r1, r2, r3, bo + OF_BH + boff + ni * (16 * RS) + kb);
                bh[ni * 2][0] = r0;     bh[ni * 2][1] = r2;
                bh[ni * 2 + 1][0] = r1; bh[ni * 2 + 1][1] = r3;
                ldsm_x4(r0, r1, r2, r3, bo + OF_BL + boff + ni * (16 * RS) + kb);
                bl[ni * 2][0] = r0;     bl[ni * 2][1] = r2;
                bl[ni * 2 + 1][0] = r1; bl[ni * 2 + 1][1] = r3;
            }
#pragma unroll
            for (int mi = 0; mi < 4; mi++)
#pragma unroll
                for (int nj = 0; nj < 4; nj++)
                    mma16816(acc[mi][nj], ah[mi], bh[nj]);
#pragma unroll
            for (int mi = 0; mi < 4; mi++)
#pragma unroll
                for (int nj = 0; nj < 4; nj++)
                    mma16816(acc[mi][nj], ah[mi], bl[nj]);
#pragma unroll
            for (int mi = 0; mi < 4; mi++)
#pragma unroll
                for (int nj = 0; nj < 4; nj++)
                    mma16816(acc[mi][nj], al[mi], bh[nj]);
        }

        if ((g & 15) == 15) {
            const int hc = (g >> 4) * 128;
#pragma unroll
            for (int mi = 0; mi < 4; mi++)
#pragma unroll
                for (int nj = 0; nj < 4; nj++) {
                    const int n0 = hc + wn * 32 + nj * 8 + (lane & 3) * 2;
                    const float v0 = V_s[n0],     q0 = pre_s[n0];
                    const float v1 = V_s[n0 + 1], q1 = pre_s[n0 + 1];
                    p[mi * 2] += v0 * fast_tanh(q0 + acc[mi][nj][0])
                               + v1 * fast_tanh(q1 + acc[mi][nj][1]);
                    p[mi * 2 + 1] += v0 * fast_tanh(q0 + acc[mi][nj][2])
                                   + v1 * fast_tanh(q1 + acc[mi][nj][3]);
                    acc[mi][nj][0] = 0.f; acc[mi][nj][1] = 0.f;
                    acc[mi][nj][2] = 0.f; acc[mi][nj][3] = 0.f;
                }
        }
    }

#pragma unroll
    for (int i = 0; i < 8; i++) {
        p[i] += __shfl_xor_sync(0xffffffffu, p[i], 1);
        p[i] += __shfl_xor_sync(0xffffffffu, p[i], 2);
    }
    if ((lane & 3) == 0) {
#pragma unroll
        for (int mi = 0; mi < 4; mi++)
#pragma unroll
            for (int hf = 0; hf < 2; hf++) {
                const int row = wm * 64 + mi * 16 + (lane >> 2) + hf * 8;
                attw[wn * 128 + row] = p[mi * 2 + hf];
            }
    }
    __syncthreads();
    if (tid < 128 && s0 + tid < cnt) {
        const float a = (attw[tid] + attw[128 + tid])
                      + (attw[256 + tid] + attw[384 + tid]);
        g_att[b * Sq + g_sidx[b * Sq + s0 + tid]] = a;
    }
}

// ---------------------------------------------------------------------------
// Masked softmax (mask int32). Masked g_att entries may be garbage — the
// select replaces them with -inf before any use.
// ---------------------------------------------------------------------------
__global__ void k_softmax(const int* __restrict__ mask,
                          float* __restrict__ alpha) {
    const int b = blockIdx.x, tid = threadIdx.x;
    __shared__ float red[8];
    float v[4];
#pragma unroll
    for (int i = 0; i < 4; i++) {
        const int s = tid + i * 256;
        const float a = g_att[b * Sq + s];
        v[i] = mask[b * Sq + s] ? -INFINITY : a;
    }
    float m = fmaxf(fmaxf(v[0], v[1]), fmaxf(v[2], v[3]));
#pragma unroll
    for (int o = 16; o; o >>= 1) m = fmaxf(m, __shfl_xor_sync(~0u, m, o));
    if ((tid & 31) == 0) red[tid >> 5] = m;
    __syncthreads();
    m = red[0];
#pragma unroll
    for (int i = 1; i < 8; i++) m = fmaxf(m, red[i]);
    __syncthreads();
    float e[4], sum = 0.f;
#pragma unroll
    for (int i = 0; i < 4; i++) { e[i] = expf(v[i] - m); sum += e[i]; }
#pragma unroll
    for (int o = 16; o; o >>= 1) sum += __shfl_xor_sync(~0u, sum, o);
    if ((tid & 31) == 0) red[tid >> 5] = sum;
    __syncthreads();
    sum = 0.f;
#pragma unroll
    for (int i = 0; i < 8; i++) sum += red[i];
    const float inv = 1.f / sum;
#pragma unroll
    for (int i = 0; i < 4; i++)
        alpha[b * Sq + tid + i * 256] = e[i] * inv;
}

// ---------------------------------------------------------------------------
// c_bar partials + reduce (deterministic). alpha[masked] == 0 exactly, so
// including all rows stays correct.
// ---------------------------------------------------------------------------
__global__ void k_cbar(const float* __restrict__ context,
                       const float* __restrict__ alpha) {
    const int b  = blockIdx.z;
    const int sc = blockIdx.y;
    const int d  = blockIdx.x * 256 + threadIdx.x;
    const int s0 = sc * 256;
    __shared__ float al[256];
    al[threadIdx.x] = alpha[b * Sq + s0 + threadIdx.x];
    __syncthreads();
    const float* cp = context + ((size_t)b * Sq + s0) * Dq + d;
    float a0 = 0.f, a1 = 0.f, a2 = 0.f, a3 = 0.f;
    for (int s = 0; s < 256; s += 4) {
        a0 += al[s + 0] * cp[(size_t)(s + 0) * Dq];
        a1 += al[s + 1] * cp[(size_t)(s + 1) * Dq];
        a2 += al[s + 2] * cp[(size_t)(s + 2) * Dq];
        a3 += al[s + 3] * cp[(size_t)(s + 3) * Dq];
    }
    g_cbar_part[sc][b * Dq + d] = (a0 + a1) + (a2 + a3);
}
__global__ void k_cbar_reduce() {
    const int i = blockIdx.x * 256 + threadIdx.x;
    g_cbar[i] = (g_cbar_part[0][i] + g_cbar_part[1][i])
              + (g_cbar_part[2][i] + g_cbar_part[3][i]);
}

// ---------------------------------------------------------------------------
extern "C" void kernel_launch(void* const* d_in, const int* in_sizes, int n_in,
                              void* d_out, int out_size) {
    const float* input   = (const float*)d_in[0];
    const float* context = (const float*)d_in[1];
    const int*   mask    = (const int*)d_in[2];
    const float* W_in    = (const float*)d_in[3];
    const float* b_in    = (const float*)d_in[4];
    const float* W_ctx   = (const float*)d_in[5];
    const float* b_ctx   = (const float*)d_in[6];
    const float* V       = (const float*)d_in[7];

    float* hidden = (float*)d_out;
    float* alpha  = (float*)d_out + Bq * Hq;

    float *p_inp = nullptr, *p_cbar = nullptr;
    void  *p_ch = nullptr, *p_cl = nullptr, *p_wh = nullptr, *p_wl = nullptr;
    cudaGetSymbolAddress((void**)&p_inp,  g_inp);
    cudaGetSymbolAddress((void**)&p_cbar, g_cbar);
    cudaGetSymbolAddress(&p_ch, g_ctx_h);
    cudaGetSymbolAddress(&p_cl, g_ctx_l);
    cudaGetSymbolAddress(&p_wh, g_w_h);
    cudaGetSymbolAddress(&p_wl, g_w_l);

    cudaFuncSetAttribute(k_mma, cudaFuncAttributeMaxDynamicSharedMemorySize,
                         SMEM_SZ);

    const int n4c = Bq * Sq * Dq / 4;
    const int n4w = Hq * Dq / 4;
    k_compact  <<<Bq, 1024>>>(mask);
    k_split_ctx<<<n4c / 256, 256>>>((const float4*)context,
                                    (uint2*)p_ch, (uint2*)p_cl, mask);
    k_split_w  <<<n4w / 256, 256>>>((const float4*)W_ctx,
                                    (uint2*)p_wh, (uint2*)p_wl, n4w);
    k_lin      <<<Bq, 256>>>(input, W_in, b_in, p_inp);
    k_mma      <<<dim3(Sq / 128, Bq), 256, SMEM_SZ>>>(b_ctx, V);
    k_softmax  <<<Bq, 256>>>(mask, alpha);
    k_cbar     <<<dim3(2, 4, Bq), 256>>>(context, alpha);
    k_cbar_reduce<<<Bq * Dq / 256, 256>>>();
    k_lin      <<<Bq, 256>>>(p_cbar, W_ctx, b_ctx, hidden);
}

// round 13
// speedup vs baseline: 1.6427x; 1.0848x over previous
#include <cuda_runtime.h>
#include <cuda_bf16.h>
#include <math.h>
#include <stdint.h>

#define Bq 128
#define Sq 1024
#define Dq 512
#define Hq 512

// ---------------- scratch (device globals; no allocs allowed) ---------------
__device__ float g_inp [Bq * Hq];
__device__ float g_att [Bq * Sq];
__device__ float g_cbar_part[4][Bq * Dq];
__device__ int   g_sidx[Bq * Sq];     // compacted unmasked s-indices per b
__device__ int   g_cnt [Bq];          // unmasked count per b
__device__ __nv_bfloat16 g_ctx_h[Bq * Sq * Dq];   // 128 MB
__device__ __nv_bfloat16 g_ctx_l[Bq * Sq * Dq];   // 128 MB
__device__ __nv_bfloat16 g_w_h  [Hq * Dq];
__device__ __nv_bfloat16 g_w_l  [Hq * Dq];

// ---------------- smem layout for k_mma (bytes) ------------------------------
#define RS      80
#define TSZ     (128 * RS)          // 10240 per tile per buffer
#define OF_AH   0                   // [2][TSZ]
#define OF_AL   20480
#define OF_BH   40960
#define OF_BL   61440
#define OF_PRE  81920               // 512 floats
#define OF_V    83968               // 512 floats
#define OF_ATTW 86016               // 4 x 128 floats
#define SMEM_SZ 88064

// ---------------- PTX helpers ------------------------------------------------
__device__ __forceinline__ uint32_t smem_u32(const void* p) {
    uint32_t a;
    asm("{ .reg .u64 t; cvta.to.shared.u64 t, %1; cvt.u32.u64 %0, t; }"
        : "=r"(a) : "l"(p));
    return a;
}
__device__ __forceinline__ void cp16(uint32_t dst, const void* src) {
    asm volatile("cp.async.cg.shared.global [%0], [%1], 16;"
                 :: "r"(dst), "l"(src) : "memory");
}
__device__ __forceinline__ void cp_commit() {
    asm volatile("cp.async.commit_group;" ::: "memory");
}
__device__ __forceinline__ void cp_wait0() {
    asm volatile("cp.async.wait_group 0;" ::: "memory");
}
__device__ __forceinline__ void ldsm_x4(uint32_t& r0, uint32_t& r1,
                                        uint32_t& r2, uint32_t& r3,
                                        uint32_t addr) {
    asm volatile("ldmatrix.sync.aligned.m8n8.x4.shared.b16 {%0,%1,%2,%3}, [%4];"
                 : "=r"(r0), "=r"(r1), "=r"(r2), "=r"(r3) : "r"(addr));
}
__device__ __forceinline__ void mma16816(float* c, const uint32_t* a,
                                         const uint32_t* b) {
    asm volatile(
        "mma.sync.aligned.m16n8k16.row.col.f32.bf16.bf16.f32 "
        "{%0,%1,%2,%3}, {%4,%5,%6,%7}, {%8,%9}, {%0,%1,%2,%3};"
        : "+f"(c[0]), "+f"(c[1]), "+f"(c[2]), "+f"(c[3])
        : "r"(a[0]), "r"(a[1]), "r"(a[2]), "r"(a[3]), "r"(b[0]), "r"(b[1]));
}

// ---------------- fast tanh: FMA-only rational, no MUFU ----------------------
__device__ __forceinline__ float fast_tanh(float x) {
    x = fminf(fmaxf(x, -7.99881172f), 7.99881172f);
    const float x2 = x * x;
    float p = fmaf(x2, -2.76076847742355e-16f, 2.00018790482477e-13f);
    p = fmaf(p, x2, -8.60467152213735e-11f);
    p = fmaf(p, x2,  5.12229709037114e-08f);
    p = fmaf(p, x2,  1.48572235717979e-05f);
    p = fmaf(p, x2,  6.37261928875436e-04f);
    p = fmaf(p, x2,  4.89352455891786e-03f);
    p *= x;
    float q = fmaf(x2, 1.19825839466702e-06f, 1.18534705686654e-04f);
    q = fmaf(q, x2, 2.26843463243900e-03f);
    q = fmaf(q, x2, 4.89352518554385e-03f);
    float r = __uint_as_float(0x7EF311C3u - __float_as_uint(q));
    r = r * (2.0f - q * r);
    r = r * (2.0f - q * r);
    r = r * (2.0f - q * r);
    return p * r;
}

// ---------------------------------------------------------------------------
// k_compact: per-b stable compaction of unmasked s indices (ballot scan).
// ---------------------------------------------------------------------------
__global__ void k_compact(const int* __restrict__ mask) {
    const int b = blockIdx.x, tid = threadIdx.x;
    const int wid = tid >> 5, lane = tid & 31;
    __shared__ int wcnt[32];
    const int um = (mask[b * Sq + tid] == 0);
    const unsigned bal = __ballot_sync(0xffffffffu, um);
    if (lane == 0) wcnt[wid] = __popc(bal);
    __syncthreads();
    if (tid == 0) {
        int t = 0;
        for (int i = 0; i < 32; i++) { int c = wcnt[i]; wcnt[i] = t; t += c; }
        g_cnt[b] = t;
    }
    __syncthreads();
    if (um) {
        const int pos = wcnt[wid] + __popc(bal & ((1u << lane) - 1u));
        g_sidx[b * Sq + pos] = tid;
    }
}

// ---------------------------------------------------------------------------
// bf16 hi/lo split helpers
// ---------------------------------------------------------------------------
__device__ __forceinline__ uint32_t pack_bf2(float a, float b) {
    __nv_bfloat162 t;
    t.x = __float2bfloat16(a);
    t.y = __float2bfloat16(b);
    return *(uint32_t*)&t;
}
__device__ __forceinline__ void split4(float4 v, uint2& H, uint2& L) {
    float h0 = __bfloat162float(__float2bfloat16(v.x));
    float h1 = __bfloat162float(__float2bfloat16(v.y));
    float h2 = __bfloat162float(__float2bfloat16(v.z));
    float h3 = __bfloat162float(__float2bfloat16(v.w));
    H.x = pack_bf2(h0, h1);            H.y = pack_bf2(h2, h3);
    L.x = pack_bf2(v.x - h0, v.y - h1);
    L.y = pack_bf2(v.z - h2, v.w - h3);
}

__global__ void k_split_ctx(const float4* __restrict__ src,
                            uint2* __restrict__ dh, uint2* __restrict__ dl,
                            const int* __restrict__ mask) {
    const int i = blockIdx.x * 256 + threadIdx.x;     // n4 = 16M
    const int s = (i >> 7) & 1023;
    const int b = i >> 17;
    if (mask[b * Sq + s]) return;
    uint2 H, L;
    split4(src[i], H, L);
    dh[i] = H;  dl[i] = L;
}

__global__ void k_split_w(const float4* __restrict__ src,
                          uint2* __restrict__ dh, uint2* __restrict__ dl,
                          int n4) {
    const int i = blockIdx.x * 256 + threadIdx.x;
    if (i >= n4) return;
    uint2 H, L;
    split4(src[i], H, L);
    dh[i] = H;  dl[i] = L;
}

// ---------------------------------------------------------------------------
// k_lin: warp-per-h, lane-parallel K. grid(Bq, 4), 256 threads (8 warps).
// out[b,h] = bias[h] + dot(X[b,:], W[h,:]); each warp does 16 h values.
// ---------------------------------------------------------------------------
__device__ __forceinline__ void lin_body(const float* __restrict__ xs,
                                         const float* __restrict__ W,
                                         const float* __restrict__ bias,
                                         float* __restrict__ out,
                                         int b, int hc, int tid) {
    const int wid = tid >> 5, lane = tid & 31;
    for (int h = hc + wid; h < hc + 128; h += 8) {
        const float4* w = (const float4*)(W + (size_t)h * Dq) + lane * 4;
        float acc = 0.f;
#pragma unroll
        for (int i = 0; i < 4; i++) {
            float4 wv = w[i];
            const int x0 = lane * 16 + i * 4;
            acc += wv.x * xs[x0] + wv.y * xs[x0 + 1]
                 + wv.z * xs[x0 + 2] + wv.w * xs[x0 + 3];
        }
#pragma unroll
        for (int o = 16; o; o >>= 1) acc += __shfl_xor_sync(~0u, acc, o);
        if (lane == 0) out[b * Hq + h] = acc + bias[h];
    }
}

__global__ void k_lin(const float* __restrict__ X, const float* __restrict__ W,
                      const float* __restrict__ bias, float* __restrict__ out) {
    __shared__ float xs[Dq];
    const int b = blockIdx.x, hc = blockIdx.y * 128, tid = threadIdx.x;
    for (int d = tid; d < Dq; d += 256) xs[d] = X[b * Dq + d];
    __syncthreads();
    lin_body(xs, W, bias, out, b, hc, tid);
}

// hidden-state variant: X = sum of the 4 c_bar partials (fused reduce)
__global__ void k_lin_cb(const float* __restrict__ W,
                         const float* __restrict__ bias,
                         float* __restrict__ out) {
    __shared__ float xs[Dq];
    const int b = blockIdx.x, hc = blockIdx.y * 128, tid = threadIdx.x;
    for (int d = tid; d < Dq; d += 256) {
        const int i = b * Dq + d;
        xs[d] = (g_cbar_part[0][i] + g_cbar_part[1][i])
              + (g_cbar_part[2][i] + g_cbar_part[3][i]);
    }
    __syncthreads();
    lin_body(xs, W, bias, out, b, hc, tid);
}

// ---------------------------------------------------------------------------
// HMMA fused score GEMM over COMPACTED unmasked rows (unchanged from R12).
// ---------------------------------------------------------------------------
__global__ void __launch_bounds__(256)
k_mma(const float* __restrict__ b_ctx, const float* __restrict__ V) {
    extern __shared__ __align__(16) char smem[];
    const int b   = blockIdx.y;
    const int s0  = blockIdx.x * 128;
    const int cnt = g_cnt[b];
    if (s0 >= cnt) return;

    const uint32_t sb = smem_u32(smem);
    const int tid  = threadIdx.x;
    const int wid  = tid >> 5;
    const int lane = tid & 31;
    const int wm   = wid & 1;
    const int wn   = wid >> 1;

    float* pre_s = (float*)(smem + OF_PRE);
    float* V_s   = (float*)(smem + OF_V);
    float* attw  = (float*)(smem + OF_ATTW);

    for (int i = tid; i < Hq; i += 256) {
        pre_s[i] = g_inp[b * Hq + i] + b_ctx[i];
        V_s[i]   = V[i];
    }

    const int srow = tid >> 1;
    const int sseg = (tid & 1) * 2;
    const int gidx = s0 + srow < cnt ? s0 + srow : cnt - 1;
    const int grow = g_sidx[b * Sq + gidx];
    const uint32_t sdst = sb + (uint32_t)(srow * RS + sseg * 16);
    const __nv_bfloat16* pAh = g_ctx_h + ((size_t)(b * Sq) + grow) * Dq + sseg * 8;
    const __nv_bfloat16* pAl = g_ctx_l + ((size_t)(b * Sq) + grow) * Dq + sseg * 8;
    const __nv_bfloat16* pBh = g_w_h + (size_t)srow * Dq + sseg * 8;
    const __nv_bfloat16* pBl = g_w_l + (size_t)srow * Dq + sseg * 8;

    const uint32_t aoff = (uint32_t)((wm * 64 + (lane & 15)) * RS + (lane >> 4) * 16);
    const uint32_t boff = (uint32_t)((wn * 32 + (lane & 15)) * RS + (lane >> 4) * 16);

    float acc[4][4][4];
#pragma unroll
    for (int mi = 0; mi < 4; mi++)
#pragma unroll
        for (int nj = 0; nj < 4; nj++)
#pragma unroll
            for (int r = 0; r < 4; r++) acc[mi][nj][r] = 0.f;
    float p[8];
#pragma unroll
    for (int i = 0; i < 8; i++) p[i] = 0.f;

    __syncthreads();

    auto stage = [&](int g, int buf) {
        const int ka = (g & 15) * 32;
        const int hb = (g >> 4) * 128;
        const uint32_t d = sdst + (uint32_t)(buf * TSZ);
        const __nv_bfloat16* a_h = pAh + ka;
        const __nv_bfloat16* a_l = pAl + ka;
        const __nv_bfloat16* b_h = pBh + (size_t)hb * Dq + ka;
        const __nv_bfloat16* b_l = pBl + (size_t)hb * Dq + ka;
        cp16(d + OF_AH,      a_h);
        cp16(d + OF_AH + 16, a_h + 8);
        cp16(d + OF_AL,      a_l);
        cp16(d + OF_AL + 16, a_l + 8);
        cp16(d + OF_BH,      b_h);
        cp16(d + OF_BH + 16, b_h + 8);
        cp16(d + OF_BL,      b_l);
        cp16(d + OF_BL + 16, b_l + 8);
    };

    stage(0, 0);
    cp_commit();

    for (int g = 0; g < 64; g++) {
        const int buf = g & 1;
        cp_wait0();
        __syncthreads();
        if (g < 63) { stage(g + 1, buf ^ 1); cp_commit(); }

        const uint32_t bo = sb + (uint32_t)(buf * TSZ);
#pragma unroll
        for (int kk = 0; kk < 2; kk++) {
            const uint32_t kb = kk * 32;
            uint32_t ah[4][4], al[4][4], bh[4][2], bl[4][2];
#pragma unroll
            for (int mi = 0; mi < 4; mi++) {
                ldsm_x4(ah[mi][0], ah[mi][1], ah[mi][2], ah[mi][3],
                        bo + OF_AH + aoff + mi * (16 * RS) + kb);
                ldsm_x4(al[mi][0], al[mi][1], al[mi][2], al[mi][3],
                        bo + OF_AL + aoff + mi * (16 * RS) + kb);
            }
#pragma unroll
            for (int ni = 0; ni < 2; ni++) {
                uint32_t r0, r1, r2, r3;
                ldsm_x4(r0, r1, r2, r3, bo + OF_BH + boff + ni * (16 * RS) + kb);
                bh[ni * 2][0] = r0;     bh[ni * 2][1] = r2;
                bh[ni * 2 + 1][0] = r1; bh[ni * 2 + 1][1] = r3;
                ldsm_x4(r0, r1, r2, r3, bo + OF_BL + boff + ni * (16 * RS) + kb);
                bl[ni * 2][0] = r0;     bl[ni * 2][1] = r2;
                bl[ni * 2 + 1][0] = r1; bl[ni * 2 + 1][1] = r3;
            }
#pragma unroll
            for (int mi = 0; mi < 4; mi++)
#pragma unroll
                for (int nj = 0; nj < 4; nj++)
                    mma16816(acc[mi][nj], ah[mi], bh[nj]);
#pragma unroll
            for (int mi = 0; mi < 4; mi++)
#pragma unroll
                for (int nj = 0; nj < 4; nj++)
                    mma16816(acc[mi][nj], ah[mi], bl[nj]);
#pragma unroll
            for (int mi = 0; mi < 4; mi++)
#pragma unroll
                for (int nj = 0; nj < 4; nj++)
                    mma16816(acc[mi][nj], al[mi], bh[nj]);
        }

        if ((g & 15) == 15) {
            const int hc = (g >> 4) * 128;
#pragma unroll
            for (int mi = 0; mi < 4; mi++)
#pragma unroll
                for (int nj = 0; nj < 4; nj++) {
                    const int n0 = hc + wn * 32 + nj * 8 + (lane & 3) * 2;
                    const float v0 = V_s[n0],     q0 = pre_s[n0];
                    const float v1 = V_s[n0 + 1], q1 = pre_s[n0 + 1];
                    p[mi * 2] += v0 * fast_tanh(q0 + acc[mi][nj][0])
                               + v1 * fast_tanh(q1 + acc[mi][nj][1]);
                    p[mi * 2 + 1] += v0 * fast_tanh(q0 + acc[mi][nj][2])
                                   + v1 * fast_tanh(q1 + acc[mi][nj][3]);
                    acc[mi][nj][0] = 0.f; acc[mi][nj][1] = 0.f;
                    acc[mi][nj][2] = 0.f; acc[mi][nj][3] = 0.f;
                }
        }
    }

#pragma unroll
    for (int i = 0; i < 8; i++) {
        p[i] += __shfl_xor_sync(0xffffffffu, p[i], 1);
        p[i] += __shfl_xor_sync(0xffffffffu, p[i], 2);
    }
    if ((lane & 3) == 0) {
#pragma unroll
        for (int mi = 0; mi < 4; mi++)
#pragma unroll
            for (int hf = 0; hf < 2; hf++) {
                const int row = wm * 64 + mi * 16 + (lane >> 2) + hf * 8;
                attw[wn * 128 + row] = p[mi * 2 + hf];
            }
    }
    __syncthreads();
    if (tid < 128 && s0 + tid < cnt) {
        const float a = (attw[tid] + attw[128 + tid])
                      + (attw[256 + tid] + attw[384 + tid]);
        g_att[b * Sq + g_sidx[b * Sq + s0 + tid]] = a;
    }
}

// ---------------------------------------------------------------------------
// Masked softmax (mask int32).
// ---------------------------------------------------------------------------
__global__ void k_softmax(const int* __restrict__ mask,
                          float* __restrict__ alpha) {
    const int b = blockIdx.x, tid = threadIdx.x;
    __shared__ float red[8];
    float v[4];
#pragma unroll
    for (int i = 0; i < 4; i++) {
        const int s = tid + i * 256;
        const float a = g_att[b * Sq + s];
        v[i] = mask[b * Sq + s] ? -INFINITY : a;
    }
    float m = fmaxf(fmaxf(v[0], v[1]), fmaxf(v[2], v[3]));
#pragma unroll
    for (int o = 16; o; o >>= 1) m = fmaxf(m, __shfl_xor_sync(~0u, m, o));
    if ((tid & 31) == 0) red[tid >> 5] = m;
    __syncthreads();
    m = red[0];
#pragma unroll
    for (int i = 1; i < 8; i++) m = fmaxf(m, red[i]);
    __syncthreads();
    float e[4], sum = 0.f;
#pragma unroll
    for (int i = 0; i < 4; i++) { e[i] = expf(v[i] - m); sum += e[i]; }
#pragma unroll
    for (int o = 16; o; o >>= 1) sum += __shfl_xor_sync(~0u, sum, o);
    if ((tid & 31) == 0) red[tid >> 5] = sum;
    __syncthreads();
    sum = 0.f;
#pragma unroll
    for (int i = 0; i < 8; i++) sum += red[i];
    const float inv = 1.f / sum;
#pragma unroll
    for (int i = 0; i < 4; i++)
        alpha[b * Sq + tid + i * 256] = e[i] * inv;
}

// ---------------------------------------------------------------------------
// c_bar partials over LIVE rows only (alpha[masked]==0 exactly, so skipping
// them is exact). Chunk sc covers compacted indices [sc*n, min((sc+1)*n,cnt)).
// grid(2, 4, Bq), 256 threads.
// ---------------------------------------------------------------------------
__global__ void k_cbar(const float* __restrict__ context,
                       const float* __restrict__ alpha) {
    const int b   = blockIdx.z;
    const int sc  = blockIdx.y;
    const int d   = blockIdx.x * 256 + threadIdx.x;
    const int cnt = g_cnt[b];
    const int n   = (cnt + 3) >> 2;                  // <= 256
    const int i0  = sc * n;
    const int iN  = min(cnt - i0, n) > 0 ? min(cnt - i0, n) : 0;

    __shared__ float al[256];
    __shared__ int   ix[256];
    if ((int)threadIdx.x < iN) {
        const int s = g_sidx[b * Sq + i0 + threadIdx.x];
        ix[threadIdx.x] = s;
        al[threadIdx.x] = alpha[b * Sq + s];
    }
    __syncthreads();

    const float* cp = context + (size_t)b * Sq * Dq + d;
    float a0 = 0.f, a1 = 0.f;
    int j = 0;
    for (; j + 1 < iN; j += 2) {
        a0 += al[j]     * cp[(size_t)ix[j]     * Dq];
        a1 += al[j + 1] * cp[(size_t)ix[j + 1] * Dq];
    }
    if (j < iN) a0 += al[j] * cp[(size_t)ix[j] * Dq];
    g_cbar_part[sc][b * Dq + d] = a0 + a1;
}

// ---------------------------------------------------------------------------
extern "C" void kernel_launch(void* const* d_in, const int* in_sizes, int n_in,
                              void* d_out, int out_size) {
    const float* input   = (const float*)d_in[0];
    const float* context = (const float*)d_in[1];
    const int*   mask    = (const int*)d_in[2];
    const float* W_in    = (const float*)d_in[3];
    const float* b_in    = (const float*)d_in[4];
    const float* W_ctx   = (const float*)d_in[5];
    const float* b_ctx   = (const float*)d_in[6];
    const float* V       = (const float*)d_in[7];

    float* hidden = (float*)d_out;
    float* alpha  = (float*)d_out + Bq * Hq;

    float* p_inp = nullptr;
    void  *p_ch = nullptr, *p_cl = nullptr, *p_wh = nullptr, *p_wl = nullptr;
    cudaGetSymbolAddress((void**)&p_inp,  g_inp);
    cudaGetSymbolAddress(&p_ch, g_ctx_h);
    cudaGetSymbolAddress(&p_cl, g_ctx_l);
    cudaGetSymbolAddress(&p_wh, g_w_h);
    cudaGetSymbolAddress(&p_wl, g_w_l);

    cudaFuncSetAttribute(k_mma, cudaFuncAttributeMaxDynamicSharedMemorySize,
                         SMEM_SZ);

    const int n4c = Bq * Sq * Dq / 4;
    const int n4w = Hq * Dq / 4;
    k_compact  <<<Bq, 1024>>>(mask);
    k_split_ctx<<<n4c / 256, 256>>>((const float4*)context,
                                    (uint2*)p_ch, (uint2*)p_cl, mask);
    k_split_w  <<<n4w / 256, 256>>>((const float4*)W_ctx,
                                    (uint2*)p_wh, (uint2*)p_wl, n4w);
    k_lin      <<<dim3(Bq, 4), 256>>>(input, W_in, b_in, p_inp);
    k_mma      <<<dim3(Sq / 128, Bq), 256, SMEM_SZ>>>(b_ctx, V);
    k_softmax  <<<Bq, 256>>>(mask, alpha);
    k_cbar     <<<dim3(2, 4, Bq), 256>>>(context, alpha);
    k_lin_cb   <<<dim3(Bq, 4), 256>>>(W_ctx, b_ctx, hidden);
}